// round 11
// baseline (speedup 1.0000x reference)
#include <cuda_runtime.h>
#include <cuda_fp16.h>
#include <math.h>
#include <stdint.h>

// ---------------- problem constants ----------------
#define N_TOK 2048
#define T_DIM 512
#define H_DIM 2048
#define V_DIM 32000
#define BETAC 0.1f
#define DELTA 0.008f
#define FP8_SCALE 64.0f
#define INV_SCALE (1.0f / 4096.0f)   // 1/(64*64)

// ---------------- GEMM tiling ----------------
#define BM 128
#define BN 128
#define BK 64                     // k per stage (fp8 elems, 64B rows)
#define KTILES (H_DIM / BK)       // 32
#define NSPLIT (V_DIM / BN)       // 250
#define NGRP   (V_DIM / 16)       // 2000
#define MTILES (N_TOK / BM)       // 16
#define NSTAGE 5                  // prefetch distance 4, one barrier per tile

#define P_A 0
#define P_B 8192
#define STAGE_BYTES 16384
#define SMEM_BYTES (NSTAGE * STAGE_BYTES)   // 80KB/CTA, 2 CTA/SM

#define CAND_CAP (1 << 20)

// ---------------- device scratch ----------------
__device__ uint8_t g_Wq[V_DIM * H_DIM];
__device__ uint8_t g_rWq[V_DIM * H_DIM];
__device__ uint8_t g_Xq[N_TOK * H_DIM];
__device__ uint8_t g_rXq[N_TOK * H_DIM];

__device__ float g_pmax[N_TOK * NGRP];       // [n][group] approx 16-col maxes
__device__ float g_psum[N_TOK * 256];        // [n][split] policy exp-sums
__device__ float g_rsum[N_TOK * 256];        // [n][split] ref exp-sums
__device__ float g_lse[N_TOK];
__device__ unsigned long long g_best[N_TOK]; // packed (orderable fp32 | ~col)
__device__ float g_reflogit[N_TOK];
__device__ float g_kl[N_TOK];
__device__ int   g_ccount;
__device__ uint32_t g_cand[CAND_CAP];        // packed n<<11 | group

// ---------------- helpers ----------------
__device__ __forceinline__ uint32_t smem_u32(const void* p) {
    return (uint32_t)__cvta_generic_to_shared(p);
}
// 4 fp32 -> 4 packed e4m3 (x0 in lowest byte)
__device__ __forceinline__ uint32_t cvt4fp8(float x0, float x1, float x2, float x3) {
    uint16_t a, b;
    asm("cvt.rn.satfinite.e4m3x2.f32 %0, %1, %2;" : "=h"(a) : "f"(x1), "f"(x0));
    asm("cvt.rn.satfinite.e4m3x2.f32 %0, %1, %2;" : "=h"(b) : "f"(x3), "f"(x2));
    return (uint32_t)a | ((uint32_t)b << 16);
}
__device__ __forceinline__ void ldsm4(uint32_t* r, uint32_t addr) {
    asm volatile("ldmatrix.sync.aligned.m8n8.x4.shared.b16 {%0,%1,%2,%3}, [%4];"
                 : "=r"(r[0]), "=r"(r[1]), "=r"(r[2]), "=r"(r[3]) : "r"(addr));
}
// fp8 MMA with f16 accumulators
__device__ __forceinline__ void qmma_f16(uint32_t* c, const uint32_t* a,
                                         const uint32_t* b) {
    asm volatile(
        "mma.sync.aligned.m16n8k32.row.col.f16.e4m3.e4m3.f16 "
        "{%0,%1}, {%2,%3,%4,%5}, {%6,%7}, {%0,%1};"
        : "+r"(c[0]), "+r"(c[1])
        : "r"(a[0]), "r"(a[1]), "r"(a[2]), "r"(a[3]), "r"(b[0]), "r"(b[1]));
}
#define CP16(dst, src)                                                       \
    asm volatile("cp.async.cg.shared.global [%0], [%1], 16;" ::              \
                 "r"(dst), "l"(src) : "memory")
#define CP_COMMIT() asm volatile("cp.async.commit_group;" ::: "memory")
#define CP_WAIT()   asm volatile("cp.async.wait_group %0;" :: "n"(NSTAGE - 2) : "memory")

// swizzled byte offset: 64B rows, 16B segs XOR'd -> conflict-free ldmatrix
__device__ __forceinline__ int sw_off(int row, int seg) {
    return row * 64 + ((seg ^ ((row >> 1) & 3)) << 4);
}
__device__ __forceinline__ uint32_t fkey(float f) {   // orderable float bits
    uint32_t u = __float_as_uint(f);
    return (u & 0x80000000u) ? ~u : (u | 0x80000000u);
}

// ============================================================================
__global__ void reset_kernel() { g_ccount = 0; }

// fp32 -> e4m3 (scaled): 1 thread = 4 float4 loads -> 1 uint4 store.
__global__ void split_fp8(const float4* __restrict__ src,
                          uint4* __restrict__ dst, int n16)
{
    const int i = blockIdx.x * blockDim.x + threadIdx.x;
    if (i >= n16) return;
    const float4 a = src[4 * i];
    const float4 b = src[4 * i + 1];
    const float4 c = src[4 * i + 2];
    const float4 d = src[4 * i + 3];
    uint4 o;
    o.x = cvt4fp8(a.x * FP8_SCALE, a.y * FP8_SCALE, a.z * FP8_SCALE, a.w * FP8_SCALE);
    o.y = cvt4fp8(b.x * FP8_SCALE, b.y * FP8_SCALE, b.z * FP8_SCALE, b.w * FP8_SCALE);
    o.z = cvt4fp8(c.x * FP8_SCALE, c.y * FP8_SCALE, c.z * FP8_SCALE, c.w * FP8_SCALE);
    o.w = cvt4fp8(d.x * FP8_SCALE, d.y * FP8_SCALE, d.z * FP8_SCALE, d.w * FP8_SCALE);
    dst[i] = o;
}

// ============================================================================
// e4m3 QMMA GEMM with f16 accumulators (128x128 per CTA, full K).
// 5-stage cp.async pipeline, ONE barrier per k-tile (prefetch distance 4).
// Epilogue: exp-sum per split; if ARG, approx max per 16-col group.
// ============================================================================
template <bool ARG>
__global__ void __launch_bounds__(256, 2)
gemm_fp8(const uint8_t* __restrict__ Aq, const uint8_t* __restrict__ Bq,
         const float* __restrict__ bias)
{
    extern __shared__ __align__(1024) char smem[];
    const int tid  = threadIdx.x;
    const int lane = tid & 31;
    const int w    = tid >> 5;
    const int wm   = w & 1;          // M half (64 rows)
    const int wn   = w >> 1;         // N quarter (32 cols)
    const int m0 = blockIdx.x * BM;
    const int v0 = blockIdx.y * BN;
    const uint32_t sb = smem_u32(smem);

    // cp.async loader: 512 segs/plane (128 rows x 4x16B), 2 per thread per plane
    const int s0   = tid << 1;
    const int row0 = s0 >> 2, seg0 = s0 & 3;
    const int row1 = (s0 + 1) >> 2, seg1 = (s0 + 1) & 3;
    const size_t ga0 = (size_t)(m0 + row0) * H_DIM + (seg0 << 4);
    const size_t ga1 = (size_t)(m0 + row1) * H_DIM + (seg1 << 4);
    const size_t gb0 = (size_t)(v0 + row0) * H_DIM + (seg0 << 4);
    const size_t gb1 = (size_t)(v0 + row1) * H_DIM + (seg1 << 4);
    const int so0 = sw_off(row0, seg0);
    const int so1 = sw_off(row1, seg1);

    // ldmatrix base offsets (kk=0; kk=1 is XOR 32)
    const int r_in = lane & 7;
    int offA[4], offB[2];
    {
        const int hm = (lane >> 3) & 1, hk = lane >> 4;
#pragma unroll
        for (int mi = 0; mi < 4; mi++)
            offA[mi] = P_A + sw_off(wm * 64 + mi * 16 + hm * 8 + r_in, hk);
    }
    {
        const int hkb = (lane >> 3) & 1, hn = lane >> 4;
#pragma unroll
        for (int bi = 0; bi < 2; bi++)
            offB[bi] = P_B + sw_off(wn * 32 + bi * 16 + hn * 8 + r_in, hkb);
    }

    uint32_t c[4][4][2];            // f16x2 accumulators
#pragma unroll
    for (int i = 0; i < 4; i++)
#pragma unroll
        for (int j = 0; j < 4; j++) { c[i][j][0] = 0u; c[i][j][1] = 0u; }

    // prologue: fill NSTAGE-1 stages (tiles 0..3)
#pragma unroll
    for (int st = 0; st < NSTAGE - 1; st++) {
        const uint32_t d = sb + st * STAGE_BYTES;
        const int k0 = st * BK;
        CP16(d + P_A + so0, Aq + ga0 + k0);
        CP16(d + P_A + so1, Aq + ga1 + k0);
        CP16(d + P_B + so0, Bq + gb0 + k0);
        CP16(d + P_B + so1, Bq + gb1 + k0);
        CP_COMMIT();
    }

#pragma unroll 1
    for (int kt = 0; kt < KTILES; kt++) {
        const int cs = kt % NSTAGE;                 // consume stage
        const uint32_t stOff = cs * STAGE_BYTES;
        CP_WAIT();            // tile kt landed (<= NSTAGE-2 groups pending)
        __syncthreads();      // all warps finished computing tile kt-1

        // issue tile kt+NSTAGE-1 into stage (kt-1)%NSTAGE (freed by barrier)
        if (kt + NSTAGE - 1 < KTILES) {
            const int ps = (kt + NSTAGE - 1) % NSTAGE;
            const uint32_t d = sb + ps * STAGE_BYTES;
            const int k0 = (kt + NSTAGE - 1) * BK;
            CP16(d + P_A + so0, Aq + ga0 + k0);
            CP16(d + P_A + so1, Aq + ga1 + k0);
            CP16(d + P_B + so0, Bq + gb0 + k0);
            CP16(d + P_B + so1, Bq + gb1 + k0);
        }
        CP_COMMIT();          // commit even when empty: keeps group accounting

        // ---- compute 2 x k32 from stage cs ----
#pragma unroll
        for (int kk = 0; kk < 2; kk++) {
            const int kx = kk << 5;
            uint32_t Bh[2][4];
#pragma unroll
            for (int bi = 0; bi < 2; bi++)
                ldsm4(Bh[bi], sb + ((offB[bi] + stOff) ^ kx));
#pragma unroll
            for (int mi = 0; mi < 4; mi++) {
                uint32_t Ah[4];
                ldsm4(Ah, sb + ((offA[mi] + stOff) ^ kx));
#pragma unroll
                for (int nf = 0; nf < 4; nf++)
                    qmma_f16(c[mi][nf], Ah, &Bh[nf >> 1][(nf & 1) * 2]);
            }
        }
    }

    // ---- epilogue ----
    const int g = lane >> 2, t = lane & 3;
    float sm8[8], mx16[8][2];
#pragma unroll
    for (int i = 0; i < 8; i++) {
        sm8[i] = 0.f;
        mx16[i][0] = -INFINITY;
        mx16[i][1] = -INFINITY;
    }

#pragma unroll
    for (int mi = 0; mi < 4; mi++) {
#pragma unroll
        for (int nf = 0; nf < 4; nf++) {
            const int col0 = wn * 32 + nf * 8 + 2 * t;
            const float b0v = bias[v0 + col0];
            const float b1v = bias[v0 + col0 + 1];
            const float2 lo = __half22float2(*(const __half2*)&c[mi][nf][0]);
            const float2 hi = __half22float2(*(const __half2*)&c[mi][nf][1]);
            const float x00 = lo.x * INV_SCALE + b0v;
            const float x01 = lo.y * INV_SCALE + b1v;
            const float x10 = hi.x * INV_SCALE + b0v;
            const float x11 = hi.y * INV_SCALE + b1v;
            const int sa = mi * 2, sbI = sa + 1;
            sm8[sa]  += __expf(x00) + __expf(x01);
            sm8[sbI] += __expf(x10) + __expf(x11);
            if (ARG) {
                const int h = nf >> 1;
                mx16[sa][h]  = fmaxf(mx16[sa][h],  fmaxf(x00, x01));
                mx16[sbI][h] = fmaxf(mx16[sbI][h], fmaxf(x10, x11));
            }
        }
    }

    // quad reduce over t
#pragma unroll
    for (int i = 0; i < 8; i++) {
        float s = sm8[i];
        s += __shfl_xor_sync(0xFFFFFFFFu, s, 1);
        s += __shfl_xor_sync(0xFFFFFFFFu, s, 2);
        sm8[i] = s;
        if (ARG) {
#pragma unroll
            for (int h = 0; h < 2; h++) {
                float m = mx16[i][h];
                m = fmaxf(m, __shfl_xor_sync(0xFFFFFFFFu, m, 1));
                m = fmaxf(m, __shfl_xor_sync(0xFFFFFFFFu, m, 2));
                mx16[i][h] = m;
            }
        }
    }

    if (ARG && t == 0) {
        const int gb = blockIdx.y * 8 + wn * 2;
#pragma unroll
        for (int mi = 0; mi < 4; mi++)
#pragma unroll
            for (int hr = 0; hr < 2; hr++) {
                const int rowc = wm * 64 + mi * 16 + hr * 8 + g;
                const int i = mi * 2 + hr;
                g_pmax[(size_t)(m0 + rowc) * NGRP + gb]     = mx16[i][0];
                g_pmax[(size_t)(m0 + rowc) * NGRP + gb + 1] = mx16[i][1];
            }
    }

    // sums: cross-warp combine over 4 quarters via smem
    float* rS = (float*)(smem);           // [3][128]
    __syncthreads();
    if (t == 0 && wn != 0) {
#pragma unroll
        for (int mi = 0; mi < 4; mi++)
#pragma unroll
            for (int hr = 0; hr < 2; hr++) {
                const int rowc = wm * 64 + mi * 16 + hr * 8 + g;
                rS[(wn - 1) * 128 + rowc] = sm8[mi * 2 + hr];
            }
    }
    __syncthreads();
    if (t == 0 && wn == 0) {
#pragma unroll
        for (int mi = 0; mi < 4; mi++)
#pragma unroll
            for (int hr = 0; hr < 2; hr++) {
                const int rowc = wm * 64 + mi * 16 + hr * 8 + g;
                float s = sm8[mi * 2 + hr];
#pragma unroll
                for (int q = 0; q < 3; q++) s += rS[q * 128 + rowc];
                if (ARG) g_psum[(size_t)(m0 + rowc) * 256 + blockIdx.y] = s;
                else     g_rsum[(size_t)(m0 + rowc) * 256 + blockIdx.y] = s;
            }
    }
}

// ============================================================================
// Per token (one warp): approx max, lse, init best, emit candidate groups
// ============================================================================
__global__ void combine_kernel() {
    const int lane = threadIdx.x & 31;
    const int n = blockIdx.x * 8 + (threadIdx.x >> 5);

    float m = -INFINITY;
    for (int g = lane; g < NGRP; g += 32)
        m = fmaxf(m, g_pmax[(size_t)n * NGRP + g]);
#pragma unroll
    for (int off = 16; off >= 1; off >>= 1)
        m = fmaxf(m, __shfl_xor_sync(0xFFFFFFFFu, m, off));

    float s = 0.f;
    for (int sp = lane; sp < NSPLIT; sp += 32)
        s += g_psum[(size_t)n * 256 + sp];
#pragma unroll
    for (int off = 16; off >= 1; off >>= 1)
        s += __shfl_xor_sync(0xFFFFFFFFu, s, off);

    if (lane == 0) {
        g_lse[n] = logf(s);
        g_best[n] = 0ULL;
    }

    const float thr = m - DELTA;
    for (int g = lane; g < NGRP; g += 32) {
        const bool c = g_pmax[(size_t)n * NGRP + g] >= thr;
        const unsigned b = __ballot_sync(0xFFFFFFFFu, c);
        if (b == 0) continue;
        int base = 0;
        if (lane == 0) base = atomicAdd(&g_ccount, __popc(b));
        base = __shfl_sync(0xFFFFFFFFu, base, 0);
        if (c) {
            const int idx = base + __popc(b & ((1u << lane) - 1));
            if (idx < CAND_CAP) g_cand[idx] = ((uint32_t)n << 11) | (uint32_t)g;
        }
    }
}

// ============================================================================
// Exact fp32 recompute of candidate 16-col groups; atomicMax packed result
// ============================================================================
__global__ void fixup_kernel(const float* __restrict__ X,
                             const float* __restrict__ W,
                             const float* __restrict__ bias)
{
    int cnt = g_ccount;
    if (cnt > CAND_CAP) cnt = CAND_CAP;
    const int tid = threadIdx.x;
    const int colo = tid >> 3;     // 0..15
    const int sub  = tid & 7;

    for (int i = blockIdx.x; i < cnt; i += gridDim.x) {
        const uint32_t e = g_cand[i];
        const int n = e >> 11;
        const int g = e & 2047;
        const int vcol = g * 16 + colo;
        const float4* xr = (const float4*)(X + (size_t)n * H_DIM);
        const float4* wr = (const float4*)(W + (size_t)vcol * H_DIM);
        float s = 0.f;
#pragma unroll 8
        for (int j = 0; j < 64; j++) {
            const int idx = j * 8 + sub;
            const float4 a = xr[idx], b = wr[idx];
            s += a.x * b.x + a.y * b.y + a.z * b.z + a.w * b.w;
        }
#pragma unroll
        for (int off = 4; off >= 1; off >>= 1)
            s += __shfl_down_sync(0xFFFFFFFFu, s, off, 8);
        if (sub == 0) {
            const float val = s + bias[vcol];
            const unsigned long long pk =
                ((unsigned long long)fkey(val) << 32) |
                (unsigned long long)(0xFFFFFFFFu - (uint32_t)vcol);
            atomicMax(&g_best[n], pk);
        }
    }
}

// ============================================================================
// Per token: exact ref dot at chosen (needs only g_best; overlaps gemm_r)
// ============================================================================
__global__ void refdot_kernel(const float* __restrict__ refX,
                              const float* __restrict__ refW,
                              const float* __restrict__ refBias)
{
    __shared__ float red[128];
    const int n = blockIdx.x;
    const int tid = threadIdx.x;
    const int chosen = (int)(0xFFFFFFFFu - (uint32_t)(g_best[n] & 0xFFFFFFFFu));

    const float4* xa = (const float4*)(refX + (size_t)n * H_DIM);
    const float4* wa = (const float4*)(refW + (size_t)chosen * H_DIM);
    float s = 0.f;
#pragma unroll
    for (int i = tid; i < H_DIM / 4; i += 128) {
        const float4 a = xa[i], w = wa[i];
        s += a.x * w.x + a.y * w.y + a.z * w.z + a.w * w.w;
    }
    red[tid] = s;
    __syncthreads();
    for (int st = 64; st >= 1; st >>= 1) {
        if (tid < st) red[tid] += red[tid + st];
        __syncthreads();
    }
    if (tid == 0) g_reflogit[n] = red[0] + refBias[chosen];
}

// ============================================================================
// Per token (one warp): ref lse from rsum + KL (tiny, after join)
// ============================================================================
__global__ void kl_kernel() {
    const int lane = threadIdx.x & 31;
    const int n = blockIdx.x * 8 + (threadIdx.x >> 5);

    float rs = 0.f;
    for (int sp = lane; sp < NSPLIT; sp += 32)
        rs += g_rsum[(size_t)n * 256 + sp];
#pragma unroll
    for (int off = 16; off >= 1; off >>= 1)
        rs += __shfl_xor_sync(0xFFFFFFFFu, rs, off);

    if (lane == 0) {
        const unsigned long long p = g_best[n];
        const uint32_t key = (uint32_t)(p >> 32);
        const uint32_t ub = (key & 0x80000000u) ? (key & 0x7FFFFFFFu) : ~key;
        const float best_val = __uint_as_float(ub);
        const float tok_lp = best_val - g_lse[n];
        const float d = (g_reflogit[n] - logf(rs)) - tok_lp;
        g_kl[n] = expm1f(d) - d;
    }
}

// ============================================================================
__global__ void finalize_kernel(const float* __restrict__ mask,
                                const float* __restrict__ rewards,
                                float* __restrict__ out)
{
    __shared__ float sl[256];
    __shared__ float sw[256];
    const int tid = threadIdx.x;
    const double r0 = rewards[0], r1 = rewards[1], r2 = rewards[2], r3 = rewards[3];
    const double mean = (r0 + r1 + r2 + r3) * 0.25;
    const double d0 = r0 - mean, d1 = r1 - mean, d2 = r2 - mean, d3 = r3 - mean;
    const double sd = sqrt((d0 * d0 + d1 * d1 + d2 * d2 + d3 * d3) / 3.0) + 1e-4;
    const float adv[4] = {(float)(d0 / sd), (float)(d1 / sd),
                          (float)(d2 / sd), (float)(d3 / sd)};
    float accL = 0.f, accW = 0.f;
    for (int n = tid; n < N_TOK; n += 256) {
        const float mk = mask[n];
        const int b = n / T_DIM;
        accL += (BETAC * g_kl[n] - adv[b]) * mk;
        accW += mk;
    }
    sl[tid] = accL;
    sw[tid] = accW;
    __syncthreads();
    for (int st = 128; st >= 1; st >>= 1) {
        if (tid < st) { sl[tid] += sl[tid + st]; sw[tid] += sw[tid + st]; }
        __syncthreads();
    }
    if (tid == 0) out[0] = sl[0] / fmaxf(sw[0], 1.0f);
}

// ============================================================================
extern "C" void kernel_launch(void* const* d_in, const int* in_sizes, int n_in,
                              void* d_out, int out_size)
{
    const float* X   = (const float*)d_in[0];
    const float* W   = (const float*)d_in[1];
    const float* msk = (const float*)d_in[2];
    const float* rwd = (const float*)d_in[3];
    const float* bs  = (const float*)d_in[4];
    const float* rX  = (const float*)d_in[5];
    const float* rW  = (const float*)d_in[6];
    const float* rbs = (const float*)d_in[7];
    float* out = (float*)d_out;

    static uint8_t *pWq = nullptr, *prWq, *pXq, *prXq;
    static cudaStream_t s1 = nullptr;
    static cudaEvent_t evF = nullptr, evP = nullptr, evJ = nullptr;
    if (!pWq) {
        cudaGetSymbolAddress((void**)&pWq,  g_Wq);
        cudaGetSymbolAddress((void**)&prWq, g_rWq);
        cudaGetSymbolAddress((void**)&pXq,  g_Xq);
        cudaGetSymbolAddress((void**)&prXq, g_rXq);
        cudaFuncSetAttribute(gemm_fp8<true>,  cudaFuncAttributeMaxDynamicSharedMemorySize, SMEM_BYTES);
        cudaFuncSetAttribute(gemm_fp8<false>, cudaFuncAttributeMaxDynamicSharedMemorySize, SMEM_BYTES);
        cudaStreamCreateWithFlags(&s1, cudaStreamNonBlocking);
        cudaEventCreateWithFlags(&evF, cudaEventDisableTiming);
        cudaEventCreateWithFlags(&evP, cudaEventDisableTiming);
        cudaEventCreateWithFlags(&evJ, cudaEventDisableTiming);
    }

    const int w16 = V_DIM * H_DIM / 16;   // 16000 blocks
    const int x16 = N_TOK * H_DIM / 16;   // 1024 blocks
    dim3 g1(MTILES, NSPLIT);

    // ---- policy pipeline first: splits alone, then gemm_p ----
    reset_kernel<<<1, 1>>>();
    split_fp8<<<w16 / 256, 256>>>((const float4*)W, (uint4*)pWq, w16);
    split_fp8<<<x16 / 256, 256>>>((const float4*)X, (uint4*)pXq, x16);
    cudaEventRecord(evF, 0);              // policy splits done (DRAM free again)
    gemm_fp8<true><<<g1, 256, SMEM_BYTES>>>(pXq, pWq, bs);
    cudaEventRecord(evP, 0);              // gemm_p done

    // ---- ref splits hide under gemm_p (tensor-bound, DRAM idle) ----
    cudaStreamWaitEvent(s1, evF, 0);
    split_fp8<<<w16 / 256, 256, 0, s1>>>((const float4*)rW, (uint4*)prWq, w16);
    split_fp8<<<x16 / 256, 256, 0, s1>>>((const float4*)rX, (uint4*)prXq, x16);

    // ---- gemm_r starts only after gemm_p (no tensor-pipe sharing) ----
    cudaStreamWaitEvent(s1, evP, 0);
    gemm_fp8<false><<<g1, 256, SMEM_BYTES, s1>>>(prXq, prWq, rbs);
    cudaEventRecord(evJ, s1);

    // ---- combine + fixup + refdot hide under gemm_r ----
    combine_kernel<<<N_TOK / 8, 256>>>();
    fixup_kernel<<<2048, 128>>>(X, W, bs);
    refdot_kernel<<<N_TOK, 128>>>(rX, rW, rbs);

    // ---- join: tiny tail ----
    cudaStreamWaitEvent(0, evJ, 0);
    kl_kernel<<<N_TOK / 8, 256>>>();
    finalize_kernel<<<1, 256>>>(msk, rwd, out);
}

// round 12
// speedup vs baseline: 1.0204x; 1.0204x over previous
#include <cuda_runtime.h>
#include <cuda_fp16.h>
#include <math.h>
#include <stdint.h>

// ---------------- problem constants ----------------
#define N_TOK 2048
#define T_DIM 512
#define H_DIM 2048
#define V_DIM 32000
#define BETAC 0.1f
#define DELTA 0.008f
#define FP8_SCALE 64.0f
#define INV_SCALE (1.0f / 4096.0f)   // 1/(64*64)

// ---------------- GEMM tiling ----------------
#define BM 128
#define BN 128
#define BK 64                     // k per stage (fp8 elems, 64B rows)
#define KTILES (H_DIM / BK)       // 32
#define NSPLIT (V_DIM / BN)       // 250
#define NGRP   (V_DIM / 16)       // 2000
#define MTILES (N_TOK / BM)       // 16
#define NSTAGE 4                  // power-of-2: cheap & masks; 1 barrier/tile

#define P_A 0
#define P_B 8192
#define STAGE_BYTES 16384
#define SMEM_BYTES (NSTAGE * STAGE_BYTES)   // 64KB/CTA, 2 CTA/SM

#define CAND_CAP (1 << 20)

// ---------------- device scratch ----------------
__device__ uint8_t g_Wq[V_DIM * H_DIM];
__device__ uint8_t g_rWq[V_DIM * H_DIM];
__device__ uint8_t g_Xq[N_TOK * H_DIM];
__device__ uint8_t g_rXq[N_TOK * H_DIM];

__device__ float g_pmax[N_TOK * NGRP];       // [n][group] approx 16-col maxes
__device__ float g_psum[N_TOK * 256];        // [n][split] policy exp-sums
__device__ float g_rsum[N_TOK * 256];        // [n][split] ref exp-sums
__device__ float g_lse[N_TOK];
__device__ unsigned long long g_best[N_TOK]; // packed (orderable fp32 | ~col)
__device__ float g_reflogit[N_TOK];
__device__ float g_kl[N_TOK];
__device__ int   g_ccount;
__device__ uint32_t g_cand[CAND_CAP];        // packed n<<11 | group

// ---------------- helpers ----------------
__device__ __forceinline__ uint32_t smem_u32(const void* p) {
    return (uint32_t)__cvta_generic_to_shared(p);
}
// 4 fp32 -> 4 packed e4m3 (x0 in lowest byte)
__device__ __forceinline__ uint32_t cvt4fp8(float x0, float x1, float x2, float x3) {
    uint16_t a, b;
    asm("cvt.rn.satfinite.e4m3x2.f32 %0, %1, %2;" : "=h"(a) : "f"(x1), "f"(x0));
    asm("cvt.rn.satfinite.e4m3x2.f32 %0, %1, %2;" : "=h"(b) : "f"(x3), "f"(x2));
    return (uint32_t)a | ((uint32_t)b << 16);
}
__device__ __forceinline__ void ldsm4(uint32_t* r, uint32_t addr) {
    asm volatile("ldmatrix.sync.aligned.m8n8.x4.shared.b16 {%0,%1,%2,%3}, [%4];"
                 : "=r"(r[0]), "=r"(r[1]), "=r"(r[2]), "=r"(r[3]) : "r"(addr));
}
// fp8 MMA with f16 accumulators
__device__ __forceinline__ void qmma_f16(uint32_t* c, const uint32_t* a,
                                         const uint32_t* b) {
    asm volatile(
        "mma.sync.aligned.m16n8k32.row.col.f16.e4m3.e4m3.f16 "
        "{%0,%1}, {%2,%3,%4,%5}, {%6,%7}, {%0,%1};"
        : "+r"(c[0]), "+r"(c[1])
        : "r"(a[0]), "r"(a[1]), "r"(a[2]), "r"(a[3]), "r"(b[0]), "r"(b[1]));
}
#define CP16(dst, src)                                                       \
    asm volatile("cp.async.cg.shared.global [%0], [%1], 16;" ::              \
                 "r"(dst), "l"(src) : "memory")
#define CP_COMMIT() asm volatile("cp.async.commit_group;" ::: "memory")
#define CP_WAIT()   asm volatile("cp.async.wait_group %0;" :: "n"(NSTAGE - 2) : "memory")

// swizzled byte offset: 64B rows, 16B segs XOR'd -> conflict-free ldmatrix
__device__ __forceinline__ int sw_off(int row, int seg) {
    return row * 64 + ((seg ^ ((row >> 1) & 3)) << 4);
}
__device__ __forceinline__ uint32_t fkey(float f) {   // orderable float bits
    uint32_t u = __float_as_uint(f);
    return (u & 0x80000000u) ? ~u : (u | 0x80000000u);
}

// ============================================================================
__global__ void reset_kernel() { g_ccount = 0; }

// fp32 -> e4m3 (scaled): 1 thread = 4 float4 loads -> 1 uint4 store.
__global__ void split_fp8(const float4* __restrict__ src,
                          uint4* __restrict__ dst, int n16)
{
    const int i = blockIdx.x * blockDim.x + threadIdx.x;
    if (i >= n16) return;
    const float4 a = src[4 * i];
    const float4 b = src[4 * i + 1];
    const float4 c = src[4 * i + 2];
    const float4 d = src[4 * i + 3];
    uint4 o;
    o.x = cvt4fp8(a.x * FP8_SCALE, a.y * FP8_SCALE, a.z * FP8_SCALE, a.w * FP8_SCALE);
    o.y = cvt4fp8(b.x * FP8_SCALE, b.y * FP8_SCALE, b.z * FP8_SCALE, b.w * FP8_SCALE);
    o.z = cvt4fp8(c.x * FP8_SCALE, c.y * FP8_SCALE, c.z * FP8_SCALE, c.w * FP8_SCALE);
    o.w = cvt4fp8(d.x * FP8_SCALE, d.y * FP8_SCALE, d.z * FP8_SCALE, d.w * FP8_SCALE);
    dst[i] = o;
}

// ============================================================================
// e4m3 QMMA GEMM with f16 accumulators (128x128 per CTA, full K).
// 4-stage cp.async pipeline, one barrier per k-tile, and software-pipelined
// A fragments (prefetch A[mi+1] under the MMAs of mi -> no exposed LDSM RAW).
// Epilogue: exp-sum per split; if ARG, approx max per 16-col group.
// ============================================================================
template <bool ARG>
__global__ void __launch_bounds__(256, 2)
gemm_fp8(const uint8_t* __restrict__ Aq, const uint8_t* __restrict__ Bq,
         const float* __restrict__ bias)
{
    extern __shared__ __align__(1024) char smem[];
    const int tid  = threadIdx.x;
    const int lane = tid & 31;
    const int w    = tid >> 5;
    const int wm   = w & 1;          // M half (64 rows)
    const int wn   = w >> 1;         // N quarter (32 cols)
    const int m0 = blockIdx.x * BM;
    const int v0 = blockIdx.y * BN;
    const uint32_t sb = smem_u32(smem);

    // cp.async loader: 512 segs/plane (128 rows x 4x16B), 2 per thread per plane
    const int s0   = tid << 1;
    const int row0 = s0 >> 2, seg0 = s0 & 3;
    const int row1 = (s0 + 1) >> 2, seg1 = (s0 + 1) & 3;
    const size_t ga0 = (size_t)(m0 + row0) * H_DIM + (seg0 << 4);
    const size_t ga1 = (size_t)(m0 + row1) * H_DIM + (seg1 << 4);
    const size_t gb0 = (size_t)(v0 + row0) * H_DIM + (seg0 << 4);
    const size_t gb1 = (size_t)(v0 + row1) * H_DIM + (seg1 << 4);
    const int so0 = sw_off(row0, seg0);
    const int so1 = sw_off(row1, seg1);

    // ldmatrix base offsets (kk=0; kk=1 is XOR 32)
    const int r_in = lane & 7;
    int offA[4], offB[2];
    {
        const int hm = (lane >> 3) & 1, hk = lane >> 4;
#pragma unroll
        for (int mi = 0; mi < 4; mi++)
            offA[mi] = P_A + sw_off(wm * 64 + mi * 16 + hm * 8 + r_in, hk);
    }
    {
        const int hkb = (lane >> 3) & 1, hn = lane >> 4;
#pragma unroll
        for (int bi = 0; bi < 2; bi++)
            offB[bi] = P_B + sw_off(wn * 32 + bi * 16 + hn * 8 + r_in, hkb);
    }

    uint32_t c[4][4][2];            // f16x2 accumulators
#pragma unroll
    for (int i = 0; i < 4; i++)
#pragma unroll
        for (int j = 0; j < 4; j++) { c[i][j][0] = 0u; c[i][j][1] = 0u; }

    // prologue: fill NSTAGE-1 stages (tiles 0..2)
#pragma unroll
    for (int st = 0; st < NSTAGE - 1; st++) {
        const uint32_t d = sb + st * STAGE_BYTES;
        const int k0 = st * BK;
        CP16(d + P_A + so0, Aq + ga0 + k0);
        CP16(d + P_A + so1, Aq + ga1 + k0);
        CP16(d + P_B + so0, Bq + gb0 + k0);
        CP16(d + P_B + so1, Bq + gb1 + k0);
        CP_COMMIT();
    }

#pragma unroll 1
    for (int kt = 0; kt < KTILES; kt++) {
        const uint32_t stOff = (kt & (NSTAGE - 1)) * STAGE_BYTES;
        CP_WAIT();            // tile kt landed (<= NSTAGE-2 groups pending)
        __syncthreads();      // all warps done computing tile kt-1

        // issue tile kt+NSTAGE-1 into the stage freed by the barrier
        if (kt + NSTAGE - 1 < KTILES) {
            const uint32_t d = sb + ((kt + NSTAGE - 1) & (NSTAGE - 1)) * STAGE_BYTES;
            const int k0 = (kt + NSTAGE - 1) * BK;
            CP16(d + P_A + so0, Aq + ga0 + k0);
            CP16(d + P_A + so1, Aq + ga1 + k0);
            CP16(d + P_B + so0, Bq + gb0 + k0);
            CP16(d + P_B + so1, Bq + gb1 + k0);
        }
        CP_COMMIT();          // commit even when empty: keeps group accounting

        // ---- compute 2 x k32 from this stage, A fragments double-buffered ----
#pragma unroll
        for (int kk = 0; kk < 2; kk++) {
            const int kx = kk << 5;
            uint32_t Bh[2][4];
            ldsm4(Bh[0], sb + ((offB[0] + stOff) ^ kx));
            ldsm4(Bh[1], sb + ((offB[1] + stOff) ^ kx));
            uint32_t Abuf[2][4];
            ldsm4(Abuf[0], sb + ((offA[0] + stOff) ^ kx));
#pragma unroll
            for (int mi = 0; mi < 4; mi++) {
                if (mi < 3)   // prefetch next A under this mi's MMAs
                    ldsm4(Abuf[(mi + 1) & 1], sb + ((offA[mi + 1] + stOff) ^ kx));
                const uint32_t* Ah = Abuf[mi & 1];
#pragma unroll
                for (int nf = 0; nf < 4; nf++)
                    qmma_f16(c[mi][nf], Ah, &Bh[nf >> 1][(nf & 1) * 2]);
            }
        }
    }

    // ---- epilogue ----
    const int g = lane >> 2, t = lane & 3;
    float sm8[8], mx16[8][2];
#pragma unroll
    for (int i = 0; i < 8; i++) {
        sm8[i] = 0.f;
        mx16[i][0] = -INFINITY;
        mx16[i][1] = -INFINITY;
    }

#pragma unroll
    for (int mi = 0; mi < 4; mi++) {
#pragma unroll
        for (int nf = 0; nf < 4; nf++) {
            const int col0 = wn * 32 + nf * 8 + 2 * t;
            const float b0v = bias[v0 + col0];
            const float b1v = bias[v0 + col0 + 1];
            const float2 lo = __half22float2(*(const __half2*)&c[mi][nf][0]);
            const float2 hi = __half22float2(*(const __half2*)&c[mi][nf][1]);
            const float x00 = lo.x * INV_SCALE + b0v;
            const float x01 = lo.y * INV_SCALE + b1v;
            const float x10 = hi.x * INV_SCALE + b0v;
            const float x11 = hi.y * INV_SCALE + b1v;
            const int sa = mi * 2, sbI = sa + 1;
            sm8[sa]  += __expf(x00) + __expf(x01);
            sm8[sbI] += __expf(x10) + __expf(x11);
            if (ARG) {
                const int h = nf >> 1;
                mx16[sa][h]  = fmaxf(mx16[sa][h],  fmaxf(x00, x01));
                mx16[sbI][h] = fmaxf(mx16[sbI][h], fmaxf(x10, x11));
            }
        }
    }

    // quad reduce over t
#pragma unroll
    for (int i = 0; i < 8; i++) {
        float s = sm8[i];
        s += __shfl_xor_sync(0xFFFFFFFFu, s, 1);
        s += __shfl_xor_sync(0xFFFFFFFFu, s, 2);
        sm8[i] = s;
        if (ARG) {
#pragma unroll
            for (int h = 0; h < 2; h++) {
                float m = mx16[i][h];
                m = fmaxf(m, __shfl_xor_sync(0xFFFFFFFFu, m, 1));
                m = fmaxf(m, __shfl_xor_sync(0xFFFFFFFFu, m, 2));
                mx16[i][h] = m;
            }
        }
    }

    if (ARG && t == 0) {
        const int gb = blockIdx.y * 8 + wn * 2;
#pragma unroll
        for (int mi = 0; mi < 4; mi++)
#pragma unroll
            for (int hr = 0; hr < 2; hr++) {
                const int rowc = wm * 64 + mi * 16 + hr * 8 + g;
                const int i = mi * 2 + hr;
                g_pmax[(size_t)(m0 + rowc) * NGRP + gb]     = mx16[i][0];
                g_pmax[(size_t)(m0 + rowc) * NGRP + gb + 1] = mx16[i][1];
            }
    }

    // sums: cross-warp combine over 4 quarters via smem
    float* rS = (float*)(smem);           // [3][128]
    __syncthreads();
    if (t == 0 && wn != 0) {
#pragma unroll
        for (int mi = 0; mi < 4; mi++)
#pragma unroll
            for (int hr = 0; hr < 2; hr++) {
                const int rowc = wm * 64 + mi * 16 + hr * 8 + g;
                rS[(wn - 1) * 128 + rowc] = sm8[mi * 2 + hr];
            }
    }
    __syncthreads();
    if (t == 0 && wn == 0) {
#pragma unroll
        for (int mi = 0; mi < 4; mi++)
#pragma unroll
            for (int hr = 0; hr < 2; hr++) {
                const int rowc = wm * 64 + mi * 16 + hr * 8 + g;
                float s = sm8[mi * 2 + hr];
#pragma unroll
                for (int q = 0; q < 3; q++) s += rS[q * 128 + rowc];
                if (ARG) g_psum[(size_t)(m0 + rowc) * 256 + blockIdx.y] = s;
                else     g_rsum[(size_t)(m0 + rowc) * 256 + blockIdx.y] = s;
            }
    }
}

// ============================================================================
// Per token (one warp): approx max, lse, init best, emit candidate groups
// ============================================================================
__global__ void combine_kernel() {
    const int lane = threadIdx.x & 31;
    const int n = blockIdx.x * 8 + (threadIdx.x >> 5);

    float m = -INFINITY;
    for (int g = lane; g < NGRP; g += 32)
        m = fmaxf(m, g_pmax[(size_t)n * NGRP + g]);
#pragma unroll
    for (int off = 16; off >= 1; off >>= 1)
        m = fmaxf(m, __shfl_xor_sync(0xFFFFFFFFu, m, off));

    float s = 0.f;
    for (int sp = lane; sp < NSPLIT; sp += 32)
        s += g_psum[(size_t)n * 256 + sp];
#pragma unroll
    for (int off = 16; off >= 1; off >>= 1)
        s += __shfl_xor_sync(0xFFFFFFFFu, s, off);

    if (lane == 0) {
        g_lse[n] = logf(s);
        g_best[n] = 0ULL;
    }

    const float thr = m - DELTA;
    for (int g = lane; g < NGRP; g += 32) {
        const bool c = g_pmax[(size_t)n * NGRP + g] >= thr;
        const unsigned b = __ballot_sync(0xFFFFFFFFu, c);
        if (b == 0) continue;
        int base = 0;
        if (lane == 0) base = atomicAdd(&g_ccount, __popc(b));
        base = __shfl_sync(0xFFFFFFFFu, base, 0);
        if (c) {
            const int idx = base + __popc(b & ((1u << lane) - 1));
            if (idx < CAND_CAP) g_cand[idx] = ((uint32_t)n << 11) | (uint32_t)g;
        }
    }
}

// ============================================================================
// Exact fp32 recompute of candidate 16-col groups; atomicMax packed result
// ============================================================================
__global__ void fixup_kernel(const float* __restrict__ X,
                             const float* __restrict__ W,
                             const float* __restrict__ bias)
{
    int cnt = g_ccount;
    if (cnt > CAND_CAP) cnt = CAND_CAP;
    const int tid = threadIdx.x;
    const int colo = tid >> 3;     // 0..15
    const int sub  = tid & 7;

    for (int i = blockIdx.x; i < cnt; i += gridDim.x) {
        const uint32_t e = g_cand[i];
        const int n = e >> 11;
        const int g = e & 2047;
        const int vcol = g * 16 + colo;
        const float4* xr = (const float4*)(X + (size_t)n * H_DIM);
        const float4* wr = (const float4*)(W + (size_t)vcol * H_DIM);
        float s = 0.f;
#pragma unroll 8
        for (int j = 0; j < 64; j++) {
            const int idx = j * 8 + sub;
            const float4 a = xr[idx], b = wr[idx];
            s += a.x * b.x + a.y * b.y + a.z * b.z + a.w * b.w;
        }
#pragma unroll
        for (int off = 4; off >= 1; off >>= 1)
            s += __shfl_down_sync(0xFFFFFFFFu, s, off, 8);
        if (sub == 0) {
            const float val = s + bias[vcol];
            const unsigned long long pk =
                ((unsigned long long)fkey(val) << 32) |
                (unsigned long long)(0xFFFFFFFFu - (uint32_t)vcol);
            atomicMax(&g_best[n], pk);
        }
    }
}

// ============================================================================
// Per token: exact ref dot at chosen (needs only g_best; overlaps gemm_r)
// ============================================================================
__global__ void refdot_kernel(const float* __restrict__ refX,
                              const float* __restrict__ refW,
                              const float* __restrict__ refBias)
{
    __shared__ float red[128];
    const int n = blockIdx.x;
    const int tid = threadIdx.x;
    const int chosen = (int)(0xFFFFFFFFu - (uint32_t)(g_best[n] & 0xFFFFFFFFu));

    const float4* xa = (const float4*)(refX + (size_t)n * H_DIM);
    const float4* wa = (const float4*)(refW + (size_t)chosen * H_DIM);
    float s = 0.f;
#pragma unroll
    for (int i = tid; i < H_DIM / 4; i += 128) {
        const float4 a = xa[i], w = wa[i];
        s += a.x * w.x + a.y * w.y + a.z * w.z + a.w * w.w;
    }
    red[tid] = s;
    __syncthreads();
    for (int st = 64; st >= 1; st >>= 1) {
        if (tid < st) red[tid] += red[tid + st];
        __syncthreads();
    }
    if (tid == 0) g_reflogit[n] = red[0] + refBias[chosen];
}

// ============================================================================
// Per token (one warp): ref lse from rsum + KL (tiny, after join)
// ============================================================================
__global__ void kl_kernel() {
    const int lane = threadIdx.x & 31;
    const int n = blockIdx.x * 8 + (threadIdx.x >> 5);

    float rs = 0.f;
    for (int sp = lane; sp < NSPLIT; sp += 32)
        rs += g_rsum[(size_t)n * 256 + sp];
#pragma unroll
    for (int off = 16; off >= 1; off >>= 1)
        rs += __shfl_xor_sync(0xFFFFFFFFu, rs, off);

    if (lane == 0) {
        const unsigned long long p = g_best[n];
        const uint32_t key = (uint32_t)(p >> 32);
        const uint32_t ub = (key & 0x80000000u) ? (key & 0x7FFFFFFFu) : ~key;
        const float best_val = __uint_as_float(ub);
        const float tok_lp = best_val - g_lse[n];
        const float d = (g_reflogit[n] - logf(rs)) - tok_lp;
        g_kl[n] = expm1f(d) - d;
    }
}

// ============================================================================
__global__ void finalize_kernel(const float* __restrict__ mask,
                                const float* __restrict__ rewards,
                                float* __restrict__ out)
{
    __shared__ float sl[256];
    __shared__ float sw[256];
    const int tid = threadIdx.x;
    const double r0 = rewards[0], r1 = rewards[1], r2 = rewards[2], r3 = rewards[3];
    const double mean = (r0 + r1 + r2 + r3) * 0.25;
    const double d0 = r0 - mean, d1 = r1 - mean, d2 = r2 - mean, d3 = r3 - mean;
    const double sd = sqrt((d0 * d0 + d1 * d1 + d2 * d2 + d3 * d3) / 3.0) + 1e-4;
    const float adv[4] = {(float)(d0 / sd), (float)(d1 / sd),
                          (float)(d2 / sd), (float)(d3 / sd)};
    float accL = 0.f, accW = 0.f;
    for (int n = tid; n < N_TOK; n += 256) {
        const float mk = mask[n];
        const int b = n / T_DIM;
        accL += (BETAC * g_kl[n] - adv[b]) * mk;
        accW += mk;
    }
    sl[tid] = accL;
    sw[tid] = accW;
    __syncthreads();
    for (int st = 128; st >= 1; st >>= 1) {
        if (tid < st) { sl[tid] += sl[tid + st]; sw[tid] += sw[tid + st]; }
        __syncthreads();
    }
    if (tid == 0) out[0] = sl[0] / fmaxf(sw[0], 1.0f);
}

// ============================================================================
extern "C" void kernel_launch(void* const* d_in, const int* in_sizes, int n_in,
                              void* d_out, int out_size)
{
    const float* X   = (const float*)d_in[0];
    const float* W   = (const float*)d_in[1];
    const float* msk = (const float*)d_in[2];
    const float* rwd = (const float*)d_in[3];
    const float* bs  = (const float*)d_in[4];
    const float* rX  = (const float*)d_in[5];
    const float* rW  = (const float*)d_in[6];
    const float* rbs = (const float*)d_in[7];
    float* out = (float*)d_out;

    static uint8_t *pWq = nullptr, *prWq, *pXq, *prXq;
    static cudaStream_t s1 = nullptr;
    static cudaEvent_t evF = nullptr, evP = nullptr, evJ = nullptr;
    if (!pWq) {
        cudaGetSymbolAddress((void**)&pWq,  g_Wq);
        cudaGetSymbolAddress((void**)&prWq, g_rWq);
        cudaGetSymbolAddress((void**)&pXq,  g_Xq);
        cudaGetSymbolAddress((void**)&prXq, g_rXq);
        cudaFuncSetAttribute(gemm_fp8<true>,  cudaFuncAttributeMaxDynamicSharedMemorySize, SMEM_BYTES);
        cudaFuncSetAttribute(gemm_fp8<false>, cudaFuncAttributeMaxDynamicSharedMemorySize, SMEM_BYTES);
        cudaStreamCreateWithFlags(&s1, cudaStreamNonBlocking);
        cudaEventCreateWithFlags(&evF, cudaEventDisableTiming);
        cudaEventCreateWithFlags(&evP, cudaEventDisableTiming);
        cudaEventCreateWithFlags(&evJ, cudaEventDisableTiming);
    }

    const int w16 = V_DIM * H_DIM / 16;   // 16000 blocks
    const int x16 = N_TOK * H_DIM / 16;   // 1024 blocks
    dim3 g1(MTILES, NSPLIT);

    // ---- policy pipeline first: splits alone, then gemm_p ----
    reset_kernel<<<1, 1>>>();
    split_fp8<<<w16 / 256, 256>>>((const float4*)W, (uint4*)pWq, w16);
    split_fp8<<<x16 / 256, 256>>>((const float4*)X, (uint4*)pXq, x16);
    cudaEventRecord(evF, 0);              // policy splits done (DRAM free again)
    gemm_fp8<true><<<g1, 256, SMEM_BYTES>>>(pXq, pWq, bs);
    cudaEventRecord(evP, 0);              // gemm_p done

    // ---- ref splits hide under gemm_p (tensor-bound, DRAM idle) ----
    cudaStreamWaitEvent(s1, evF, 0);
    split_fp8<<<w16 / 256, 256, 0, s1>>>((const float4*)rW, (uint4*)prWq, w16);
    split_fp8<<<x16 / 256, 256, 0, s1>>>((const float4*)rX, (uint4*)prXq, x16);

    // ---- gemm_r starts only after gemm_p (no tensor-pipe sharing) ----
    cudaStreamWaitEvent(s1, evP, 0);
    gemm_fp8<false><<<g1, 256, SMEM_BYTES, s1>>>(prXq, prWq, rbs);
    cudaEventRecord(evJ, s1);

    // ---- combine + fixup + refdot hide under gemm_r ----
    combine_kernel<<<N_TOK / 8, 256>>>();
    fixup_kernel<<<2048, 128>>>(X, W, bs);
    refdot_kernel<<<N_TOK, 128>>>(rX, rW, rbs);

    // ---- join: tiny tail ----
    cudaStreamWaitEvent(0, evJ, 0);
    kl_kernel<<<N_TOK / 8, 256>>>();
    finalize_kernel<<<1, 256>>>(msk, rwd, out);
}

// round 13
// speedup vs baseline: 1.0743x; 1.0528x over previous
#include <cuda_runtime.h>
#include <cuda_fp16.h>
#include <math.h>
#include <stdint.h>

// ---------------- problem constants ----------------
#define N_TOK 2048
#define T_DIM 512
#define H_DIM 2048
#define V_DIM 32000
#define BETAC 0.1f
#define DELTA 0.008f
#define FP8_SCALE 64.0f
#define INV_SCALE (1.0f / 4096.0f)   // 1/(64*64)

// ---------------- GEMM tiling ----------------
#define BM 128
#define BN 128
#define BK 64                     // k per stage (fp8 elems, 64B rows)
#define KTILES (H_DIM / BK)       // 32
#define NSPLIT (V_DIM / BN)       // 250
#define NGRP   (V_DIM / 16)       // 2000
#define MTILES (N_TOK / BM)       // 16
#define NSTAGE 4                  // power-of-2; 1 barrier/tile

#define P_A 0
#define P_B 8192
#define STAGE_BYTES 16384
#define SMEM_BYTES (NSTAGE * STAGE_BYTES)   // 64KB/CTA -> 3 CTA/SM = 192KB

#define CAND_CAP (1 << 20)

// ---------------- device scratch ----------------
__device__ uint8_t g_Wq[V_DIM * H_DIM];
__device__ uint8_t g_rWq[V_DIM * H_DIM];
__device__ uint8_t g_Xq[N_TOK * H_DIM];
__device__ uint8_t g_rXq[N_TOK * H_DIM];

__device__ float g_pmax[N_TOK * NGRP];       // [n][group] approx 16-col maxes
__device__ float g_psum[N_TOK * 256];        // [n][split] policy exp-sums
__device__ float g_rsum[N_TOK * 256];        // [n][split] ref exp-sums
__device__ float g_lse[N_TOK];
__device__ unsigned long long g_best[N_TOK]; // packed (orderable fp32 | ~col)
__device__ float g_reflogit[N_TOK];
__device__ float g_kl[N_TOK];
__device__ int   g_ccount;
__device__ uint32_t g_cand[CAND_CAP];        // packed n<<11 | group

// ---------------- helpers ----------------
__device__ __forceinline__ uint32_t smem_u32(const void* p) {
    return (uint32_t)__cvta_generic_to_shared(p);
}
// 4 fp32 -> 4 packed e4m3 (x0 in lowest byte)
__device__ __forceinline__ uint32_t cvt4fp8(float x0, float x1, float x2, float x3) {
    uint16_t a, b;
    asm("cvt.rn.satfinite.e4m3x2.f32 %0, %1, %2;" : "=h"(a) : "f"(x1), "f"(x0));
    asm("cvt.rn.satfinite.e4m3x2.f32 %0, %1, %2;" : "=h"(b) : "f"(x3), "f"(x2));
    return (uint32_t)a | ((uint32_t)b << 16);
}
__device__ __forceinline__ void ldsm4(uint32_t* r, uint32_t addr) {
    asm volatile("ldmatrix.sync.aligned.m8n8.x4.shared.b16 {%0,%1,%2,%3}, [%4];"
                 : "=r"(r[0]), "=r"(r[1]), "=r"(r[2]), "=r"(r[3]) : "r"(addr));
}
// fp8 MMA with f16 accumulators
__device__ __forceinline__ void qmma_f16(uint32_t* c, const uint32_t* a,
                                         const uint32_t* b) {
    asm volatile(
        "mma.sync.aligned.m16n8k32.row.col.f16.e4m3.e4m3.f16 "
        "{%0,%1}, {%2,%3,%4,%5}, {%6,%7}, {%0,%1};"
        : "+r"(c[0]), "+r"(c[1])
        : "r"(a[0]), "r"(a[1]), "r"(a[2]), "r"(a[3]), "r"(b[0]), "r"(b[1]));
}
#define CP16(dst, src)                                                       \
    asm volatile("cp.async.cg.shared.global [%0], [%1], 16;" ::              \
                 "r"(dst), "l"(src) : "memory")
#define CP_COMMIT() asm volatile("cp.async.commit_group;" ::: "memory")
#define CP_WAIT()   asm volatile("cp.async.wait_group %0;" :: "n"(NSTAGE - 2) : "memory")

// swizzled byte offset: 64B rows, 16B segs XOR'd -> conflict-free ldmatrix
__device__ __forceinline__ int sw_off(int row, int seg) {
    return row * 64 + ((seg ^ ((row >> 1) & 3)) << 4);
}
__device__ __forceinline__ uint32_t fkey(float f) {   // orderable float bits
    uint32_t u = __float_as_uint(f);
    return (u & 0x80000000u) ? ~u : (u | 0x80000000u);
}

// ============================================================================
__global__ void reset_kernel() { g_ccount = 0; }

// fp32 -> e4m3 (scaled): 1 thread = 4 float4 loads -> 1 uint4 store.
__global__ void split_fp8(const float4* __restrict__ src,
                          uint4* __restrict__ dst, int n16)
{
    const int i = blockIdx.x * blockDim.x + threadIdx.x;
    if (i >= n16) return;
    const float4 a = src[4 * i];
    const float4 b = src[4 * i + 1];
    const float4 c = src[4 * i + 2];
    const float4 d = src[4 * i + 3];
    uint4 o;
    o.x = cvt4fp8(a.x * FP8_SCALE, a.y * FP8_SCALE, a.z * FP8_SCALE, a.w * FP8_SCALE);
    o.y = cvt4fp8(b.x * FP8_SCALE, b.y * FP8_SCALE, b.z * FP8_SCALE, b.w * FP8_SCALE);
    o.z = cvt4fp8(c.x * FP8_SCALE, c.y * FP8_SCALE, c.z * FP8_SCALE, c.w * FP8_SCALE);
    o.w = cvt4fp8(d.x * FP8_SCALE, d.y * FP8_SCALE, d.z * FP8_SCALE, d.w * FP8_SCALE);
    dst[i] = o;
}

// ============================================================================
// e4m3 QMMA GEMM with f16 accumulators (128x128 per CTA, full K).
// 4-stage cp.async pipeline, one barrier per k-tile, A-fragment ping-pong.
// __launch_bounds__(256,3): <=85 regs -> 3 CTA/SM (24 warps) for latency cover.
// ============================================================================
template <bool ARG>
__global__ void __launch_bounds__(256, 3)
gemm_fp8(const uint8_t* __restrict__ Aq, const uint8_t* __restrict__ Bq,
         const float* __restrict__ bias)
{
    extern __shared__ __align__(1024) char smem[];
    const int tid  = threadIdx.x;
    const int lane = tid & 31;
    const int w    = tid >> 5;
    const int wm   = w & 1;          // M half (64 rows)
    const int wn   = w >> 1;         // N quarter (32 cols)
    const int m0 = blockIdx.x * BM;
    const int v0 = blockIdx.y * BN;
    const uint32_t sb = smem_u32(smem);

    // cp.async loader: 512 segs/plane (128 rows x 4x16B), 2 per thread per plane
    const int s0   = tid << 1;
    const int row0 = s0 >> 2, seg0 = s0 & 3;
    const int row1 = (s0 + 1) >> 2, seg1 = (s0 + 1) & 3;
    const size_t ga0 = (size_t)(m0 + row0) * H_DIM + (seg0 << 4);
    const size_t ga1 = (size_t)(m0 + row1) * H_DIM + (seg1 << 4);
    const size_t gb0 = (size_t)(v0 + row0) * H_DIM + (seg0 << 4);
    const size_t gb1 = (size_t)(v0 + row1) * H_DIM + (seg1 << 4);
    const int so0 = sw_off(row0, seg0);
    const int so1 = sw_off(row1, seg1);

    // ldmatrix base offsets (kk=0; kk=1 is XOR 32)
    const int r_in = lane & 7;
    int offA[4], offB[2];
    {
        const int hm = (lane >> 3) & 1, hk = lane >> 4;
#pragma unroll
        for (int mi = 0; mi < 4; mi++)
            offA[mi] = P_A + sw_off(wm * 64 + mi * 16 + hm * 8 + r_in, hk);
    }
    {
        const int hkb = (lane >> 3) & 1, hn = lane >> 4;
#pragma unroll
        for (int bi = 0; bi < 2; bi++)
            offB[bi] = P_B + sw_off(wn * 32 + bi * 16 + hn * 8 + r_in, hkb);
    }

    uint32_t c[4][4][2];            // f16x2 accumulators
#pragma unroll
    for (int i = 0; i < 4; i++)
#pragma unroll
        for (int j = 0; j < 4; j++) { c[i][j][0] = 0u; c[i][j][1] = 0u; }

    // prologue: fill NSTAGE-1 stages (tiles 0..2)
#pragma unroll
    for (int st = 0; st < NSTAGE - 1; st++) {
        const uint32_t d = sb + st * STAGE_BYTES;
        const int k0 = st * BK;
        CP16(d + P_A + so0, Aq + ga0 + k0);
        CP16(d + P_A + so1, Aq + ga1 + k0);
        CP16(d + P_B + so0, Bq + gb0 + k0);
        CP16(d + P_B + so1, Bq + gb1 + k0);
        CP_COMMIT();
    }

#pragma unroll 1
    for (int kt = 0; kt < KTILES; kt++) {
        const uint32_t stOff = (kt & (NSTAGE - 1)) * STAGE_BYTES;
        CP_WAIT();            // tile kt landed (<= NSTAGE-2 groups pending)
        __syncthreads();      // all warps done computing tile kt-1

        // issue tile kt+NSTAGE-1 into the stage freed by the barrier
        if (kt + NSTAGE - 1 < KTILES) {
            const uint32_t d = sb + ((kt + NSTAGE - 1) & (NSTAGE - 1)) * STAGE_BYTES;
            const int k0 = (kt + NSTAGE - 1) * BK;
            CP16(d + P_A + so0, Aq + ga0 + k0);
            CP16(d + P_A + so1, Aq + ga1 + k0);
            CP16(d + P_B + so0, Bq + gb0 + k0);
            CP16(d + P_B + so1, Bq + gb1 + k0);
        }
        CP_COMMIT();          // commit even when empty: keeps group accounting

        // ---- compute 2 x k32 from this stage, A fragments double-buffered ----
#pragma unroll
        for (int kk = 0; kk < 2; kk++) {
            const int kx = kk << 5;
            uint32_t Bh[2][4];
            ldsm4(Bh[0], sb + ((offB[0] + stOff) ^ kx));
            ldsm4(Bh[1], sb + ((offB[1] + stOff) ^ kx));
            uint32_t Abuf[2][4];
            ldsm4(Abuf[0], sb + ((offA[0] + stOff) ^ kx));
#pragma unroll
            for (int mi = 0; mi < 4; mi++) {
                if (mi < 3)   // prefetch next A under this mi's MMAs
                    ldsm4(Abuf[(mi + 1) & 1], sb + ((offA[mi + 1] + stOff) ^ kx));
                const uint32_t* Ah = Abuf[mi & 1];
#pragma unroll
                for (int nf = 0; nf < 4; nf++)
                    qmma_f16(c[mi][nf], Ah, &Bh[nf >> 1][(nf & 1) * 2]);
            }
        }
    }

    // ---- epilogue ----
    const int g = lane >> 2, t = lane & 3;
    float sm8[8], mx16[8][2];
#pragma unroll
    for (int i = 0; i < 8; i++) {
        sm8[i] = 0.f;
        mx16[i][0] = -INFINITY;
        mx16[i][1] = -INFINITY;
    }

#pragma unroll
    for (int mi = 0; mi < 4; mi++) {
#pragma unroll
        for (int nf = 0; nf < 4; nf++) {
            const int col0 = wn * 32 + nf * 8 + 2 * t;
            const float b0v = bias[v0 + col0];
            const float b1v = bias[v0 + col0 + 1];
            const float2 lo = __half22float2(*(const __half2*)&c[mi][nf][0]);
            const float2 hi = __half22float2(*(const __half2*)&c[mi][nf][1]);
            const float x00 = lo.x * INV_SCALE + b0v;
            const float x01 = lo.y * INV_SCALE + b1v;
            const float x10 = hi.x * INV_SCALE + b0v;
            const float x11 = hi.y * INV_SCALE + b1v;
            const int sa = mi * 2, sbI = sa + 1;
            sm8[sa]  += __expf(x00) + __expf(x01);
            sm8[sbI] += __expf(x10) + __expf(x11);
            if (ARG) {
                const int h = nf >> 1;
                mx16[sa][h]  = fmaxf(mx16[sa][h],  fmaxf(x00, x01));
                mx16[sbI][h] = fmaxf(mx16[sbI][h], fmaxf(x10, x11));
            }
        }
    }

    // quad reduce over t
#pragma unroll
    for (int i = 0; i < 8; i++) {
        float s = sm8[i];
        s += __shfl_xor_sync(0xFFFFFFFFu, s, 1);
        s += __shfl_xor_sync(0xFFFFFFFFu, s, 2);
        sm8[i] = s;
        if (ARG) {
#pragma unroll
            for (int h = 0; h < 2; h++) {
                float m = mx16[i][h];
                m = fmaxf(m, __shfl_xor_sync(0xFFFFFFFFu, m, 1));
                m = fmaxf(m, __shfl_xor_sync(0xFFFFFFFFu, m, 2));
                mx16[i][h] = m;
            }
        }
    }

    if (ARG && t == 0) {
        const int gb = blockIdx.y * 8 + wn * 2;
#pragma unroll
        for (int mi = 0; mi < 4; mi++)
#pragma unroll
            for (int hr = 0; hr < 2; hr++) {
                const int rowc = wm * 64 + mi * 16 + hr * 8 + g;
                const int i = mi * 2 + hr;
                g_pmax[(size_t)(m0 + rowc) * NGRP + gb]     = mx16[i][0];
                g_pmax[(size_t)(m0 + rowc) * NGRP + gb + 1] = mx16[i][1];
            }
    }

    // sums: cross-warp combine over 4 quarters via smem
    float* rS = (float*)(smem);           // [3][128]
    __syncthreads();
    if (t == 0 && wn != 0) {
#pragma unroll
        for (int mi = 0; mi < 4; mi++)
#pragma unroll
            for (int hr = 0; hr < 2; hr++) {
                const int rowc = wm * 64 + mi * 16 + hr * 8 + g;
                rS[(wn - 1) * 128 + rowc] = sm8[mi * 2 + hr];
            }
    }
    __syncthreads();
    if (t == 0 && wn == 0) {
#pragma unroll
        for (int mi = 0; mi < 4; mi++)
#pragma unroll
            for (int hr = 0; hr < 2; hr++) {
                const int rowc = wm * 64 + mi * 16 + hr * 8 + g;
                float s = sm8[mi * 2 + hr];
#pragma unroll
                for (int q = 0; q < 3; q++) s += rS[q * 128 + rowc];
                if (ARG) g_psum[(size_t)(m0 + rowc) * 256 + blockIdx.y] = s;
                else     g_rsum[(size_t)(m0 + rowc) * 256 + blockIdx.y] = s;
            }
    }
}

// ============================================================================
// Per token (one warp): approx max, lse, init best, emit candidate groups
// ============================================================================
__global__ void combine_kernel() {
    const int lane = threadIdx.x & 31;
    const int n = blockIdx.x * 8 + (threadIdx.x >> 5);

    float m = -INFINITY;
    for (int g = lane; g < NGRP; g += 32)
        m = fmaxf(m, g_pmax[(size_t)n * NGRP + g]);
#pragma unroll
    for (int off = 16; off >= 1; off >>= 1)
        m = fmaxf(m, __shfl_xor_sync(0xFFFFFFFFu, m, off));

    float s = 0.f;
    for (int sp = lane; sp < NSPLIT; sp += 32)
        s += g_psum[(size_t)n * 256 + sp];
#pragma unroll
    for (int off = 16; off >= 1; off >>= 1)
        s += __shfl_xor_sync(0xFFFFFFFFu, s, off);

    if (lane == 0) {
        g_lse[n] = logf(s);
        g_best[n] = 0ULL;
    }

    const float thr = m - DELTA;
    for (int g = lane; g < NGRP; g += 32) {
        const bool c = g_pmax[(size_t)n * NGRP + g] >= thr;
        const unsigned b = __ballot_sync(0xFFFFFFFFu, c);
        if (b == 0) continue;
        int base = 0;
        if (lane == 0) base = atomicAdd(&g_ccount, __popc(b));
        base = __shfl_sync(0xFFFFFFFFu, base, 0);
        if (c) {
            const int idx = base + __popc(b & ((1u << lane) - 1));
            if (idx < CAND_CAP) g_cand[idx] = ((uint32_t)n << 11) | (uint32_t)g;
        }
    }
}

// ============================================================================
// Exact fp32 recompute of candidate 16-col groups; atomicMax packed result
// ============================================================================
__global__ void fixup_kernel(const float* __restrict__ X,
                             const float* __restrict__ W,
                             const float* __restrict__ bias)
{
    int cnt = g_ccount;
    if (cnt > CAND_CAP) cnt = CAND_CAP;
    const int tid = threadIdx.x;
    const int colo = tid >> 3;     // 0..15
    const int sub  = tid & 7;

    for (int i = blockIdx.x; i < cnt; i += gridDim.x) {
        const uint32_t e = g_cand[i];
        const int n = e >> 11;
        const int g = e & 2047;
        const int vcol = g * 16 + colo;
        const float4* xr = (const float4*)(X + (size_t)n * H_DIM);
        const float4* wr = (const float4*)(W + (size_t)vcol * H_DIM);
        float s = 0.f;
#pragma unroll 8
        for (int j = 0; j < 64; j++) {
            const int idx = j * 8 + sub;
            const float4 a = xr[idx], b = wr[idx];
            s += a.x * b.x + a.y * b.y + a.z * b.z + a.w * b.w;
        }
#pragma unroll
        for (int off = 4; off >= 1; off >>= 1)
            s += __shfl_down_sync(0xFFFFFFFFu, s, off, 8);
        if (sub == 0) {
            const float val = s + bias[vcol];
            const unsigned long long pk =
                ((unsigned long long)fkey(val) << 32) |
                (unsigned long long)(0xFFFFFFFFu - (uint32_t)vcol);
            atomicMax(&g_best[n], pk);
        }
    }
}

// ============================================================================
// Per token: exact ref dot at chosen (needs only g_best; overlaps gemm_r)
// ============================================================================
__global__ void refdot_kernel(const float* __restrict__ refX,
                              const float* __restrict__ refW,
                              const float* __restrict__ refBias)
{
    __shared__ float red[128];
    const int n = blockIdx.x;
    const int tid = threadIdx.x;
    const int chosen = (int)(0xFFFFFFFFu - (uint32_t)(g_best[n] & 0xFFFFFFFFu));

    const float4* xa = (const float4*)(refX + (size_t)n * H_DIM);
    const float4* wa = (const float4*)(refW + (size_t)chosen * H_DIM);
    float s = 0.f;
#pragma unroll
    for (int i = tid; i < H_DIM / 4; i += 128) {
        const float4 a = xa[i], w = wa[i];
        s += a.x * w.x + a.y * w.y + a.z * w.z + a.w * w.w;
    }
    red[tid] = s;
    __syncthreads();
    for (int st = 64; st >= 1; st >>= 1) {
        if (tid < st) red[tid] += red[tid + st];
        __syncthreads();
    }
    if (tid == 0) g_reflogit[n] = red[0] + refBias[chosen];
}

// ============================================================================
// Per token (one warp): ref lse from rsum + KL (tiny, after join)
// ============================================================================
__global__ void kl_kernel() {
    const int lane = threadIdx.x & 31;
    const int n = blockIdx.x * 8 + (threadIdx.x >> 5);

    float rs = 0.f;
    for (int sp = lane; sp < NSPLIT; sp += 32)
        rs += g_rsum[(size_t)n * 256 + sp];
#pragma unroll
    for (int off = 16; off >= 1; off >>= 1)
        rs += __shfl_xor_sync(0xFFFFFFFFu, rs, off);

    if (lane == 0) {
        const unsigned long long p = g_best[n];
        const uint32_t key = (uint32_t)(p >> 32);
        const uint32_t ub = (key & 0x80000000u) ? (key & 0x7FFFFFFFu) : ~key;
        const float best_val = __uint_as_float(ub);
        const float tok_lp = best_val - g_lse[n];
        const float d = (g_reflogit[n] - logf(rs)) - tok_lp;
        g_kl[n] = expm1f(d) - d;
    }
}

// ============================================================================
__global__ void finalize_kernel(const float* __restrict__ mask,
                                const float* __restrict__ rewards,
                                float* __restrict__ out)
{
    __shared__ float sl[256];
    __shared__ float sw[256];
    const int tid = threadIdx.x;
    const double r0 = rewards[0], r1 = rewards[1], r2 = rewards[2], r3 = rewards[3];
    const double mean = (r0 + r1 + r2 + r3) * 0.25;
    const double d0 = r0 - mean, d1 = r1 - mean, d2 = r2 - mean, d3 = r3 - mean;
    const double sd = sqrt((d0 * d0 + d1 * d1 + d2 * d2 + d3 * d3) / 3.0) + 1e-4;
    const float adv[4] = {(float)(d0 / sd), (float)(d1 / sd),
                          (float)(d2 / sd), (float)(d3 / sd)};
    float accL = 0.f, accW = 0.f;
    for (int n = tid; n < N_TOK; n += 256) {
        const float mk = mask[n];
        const int b = n / T_DIM;
        accL += (BETAC * g_kl[n] - adv[b]) * mk;
        accW += mk;
    }
    sl[tid] = accL;
    sw[tid] = accW;
    __syncthreads();
    for (int st = 128; st >= 1; st >>= 1) {
        if (tid < st) { sl[tid] += sl[tid + st]; sw[tid] += sw[tid + st]; }
        __syncthreads();
    }
    if (tid == 0) out[0] = sl[0] / fmaxf(sw[0], 1.0f);
}

// ============================================================================
extern "C" void kernel_launch(void* const* d_in, const int* in_sizes, int n_in,
                              void* d_out, int out_size)
{
    const float* X   = (const float*)d_in[0];
    const float* W   = (const float*)d_in[1];
    const float* msk = (const float*)d_in[2];
    const float* rwd = (const float*)d_in[3];
    const float* bs  = (const float*)d_in[4];
    const float* rX  = (const float*)d_in[5];
    const float* rW  = (const float*)d_in[6];
    const float* rbs = (const float*)d_in[7];
    float* out = (float*)d_out;

    static uint8_t *pWq = nullptr, *prWq, *pXq, *prXq;
    static cudaStream_t s1 = nullptr;
    static cudaEvent_t evF = nullptr, evP = nullptr, evJ = nullptr;
    if (!pWq) {
        cudaGetSymbolAddress((void**)&pWq,  g_Wq);
        cudaGetSymbolAddress((void**)&prWq, g_rWq);
        cudaGetSymbolAddress((void**)&pXq,  g_Xq);
        cudaGetSymbolAddress((void**)&prXq, g_rXq);
        cudaFuncSetAttribute(gemm_fp8<true>,  cudaFuncAttributeMaxDynamicSharedMemorySize, SMEM_BYTES);
        cudaFuncSetAttribute(gemm_fp8<false>, cudaFuncAttributeMaxDynamicSharedMemorySize, SMEM_BYTES);
        cudaStreamCreateWithFlags(&s1, cudaStreamNonBlocking);
        cudaEventCreateWithFlags(&evF, cudaEventDisableTiming);
        cudaEventCreateWithFlags(&evP, cudaEventDisableTiming);
        cudaEventCreateWithFlags(&evJ, cudaEventDisableTiming);
    }

    const int w16 = V_DIM * H_DIM / 16;   // 16000 blocks
    const int x16 = N_TOK * H_DIM / 16;   // 1024 blocks
    dim3 g1(MTILES, NSPLIT);

    // ---- policy pipeline first: splits alone, then gemm_p ----
    reset_kernel<<<1, 1>>>();
    split_fp8<<<w16 / 256, 256>>>((const float4*)W, (uint4*)pWq, w16);
    split_fp8<<<x16 / 256, 256>>>((const float4*)X, (uint4*)pXq, x16);
    cudaEventRecord(evF, 0);              // policy splits done (DRAM free again)
    gemm_fp8<true><<<g1, 256, SMEM_BYTES>>>(pXq, pWq, bs);
    cudaEventRecord(evP, 0);              // gemm_p done

    // ---- ref splits hide under gemm_p (tensor-bound, DRAM idle) ----
    cudaStreamWaitEvent(s1, evF, 0);
    split_fp8<<<w16 / 256, 256, 0, s1>>>((const float4*)rW, (uint4*)prWq, w16);
    split_fp8<<<x16 / 256, 256, 0, s1>>>((const float4*)rX, (uint4*)prXq, x16);

    // ---- gemm_r starts only after gemm_p (no tensor-pipe sharing) ----
    cudaStreamWaitEvent(s1, evP, 0);
    gemm_fp8<false><<<g1, 256, SMEM_BYTES, s1>>>(prXq, prWq, rbs);
    cudaEventRecord(evJ, s1);

    // ---- combine + fixup + refdot overlap gemm_r's tail/wave gaps ----
    combine_kernel<<<N_TOK / 8, 256>>>();
    fixup_kernel<<<2048, 128>>>(X, W, bs);
    refdot_kernel<<<N_TOK, 128>>>(rX, rW, rbs);

    // ---- join: tiny tail ----
    cudaStreamWaitEvent(0, evJ, 0);
    kl_kernel<<<N_TOK / 8, 256>>>();
    finalize_kernel<<<1, 256>>>(msk, rwd, out);
}